// round 3
// baseline (speedup 1.0000x reference)
#include <cuda_runtime.h>

// Segment-sum over sorted ray_indices + gather back.
// Inputs: d_in[0] = sample_values  (float32, n_samples*8)
//         d_in[1] = ray_indices    (int32,  n_samples, sorted ascending)
//         d_in[2] = n_rays         (int32 scalar, unused; derived from sizes)
// Output: d_out[0 .. n_rays*8)                  = per-ray sums
//         d_out[n_rays*8 .. n_rays*8+n_samples*8) = per-sample gathered sums

#define RUN 16  // consecutive samples per thread in the reduce pass

__global__ void zero_kernel(float4* __restrict__ p, int n4) {
    int i = blockIdx.x * blockDim.x + threadIdx.x;
    if (i < n4) p[i] = make_float4(0.f, 0.f, 0.f, 0.f);
}

__device__ __forceinline__ void flush_ray(float* __restrict__ sums, int ray,
                                          const float4& a0, const float4& a1) {
    float* p = sums + (size_t)ray * 8;
    atomicAdd(p + 0, a0.x);
    atomicAdd(p + 1, a0.y);
    atomicAdd(p + 2, a0.z);
    atomicAdd(p + 3, a0.w);
    atomicAdd(p + 4, a1.x);
    atomicAdd(p + 5, a1.y);
    atomicAdd(p + 6, a1.z);
    atomicAdd(p + 7, a1.w);
}

__global__ void reduce_kernel(const float4* __restrict__ vals,   // 2 float4 per sample
                              const int* __restrict__ idx,
                              float* __restrict__ sums,          // [n_rays*8], pre-zeroed
                              int n_samples) {
    long long t = (long long)blockIdx.x * blockDim.x + threadIdx.x;
    long long base = t * RUN;
    if (base >= n_samples) return;

    // Load the 16 ray ids for this thread's run as 4x int4 (coalesced across the run).
    int ridx[RUN];
    const int4* idx4 = reinterpret_cast<const int4*>(idx + base);
    if (base + RUN <= n_samples) {
        #pragma unroll
        for (int q = 0; q < RUN / 4; q++) {
            int4 v = idx4[q];
            ridx[q * 4 + 0] = v.x;
            ridx[q * 4 + 1] = v.y;
            ridx[q * 4 + 2] = v.z;
            ridx[q * 4 + 3] = v.w;
        }
    } else {
        int cnt = (int)(n_samples - base);
        for (int s = 0; s < RUN; s++)
            ridx[s] = (s < cnt) ? idx[base + s] : -1;
    }

    int cnt = (int)((base + RUN <= n_samples) ? RUN : (n_samples - base));

    int cur = ridx[0];
    float4 a0 = make_float4(0.f, 0.f, 0.f, 0.f);
    float4 a1 = make_float4(0.f, 0.f, 0.f, 0.f);

    #pragma unroll
    for (int s = 0; s < RUN; s++) {
        if (s >= cnt) break;
        int r = ridx[s];
        if (r != cur) {
            flush_ray(sums, cur, a0, a1);
            cur = r;
            a0 = make_float4(0.f, 0.f, 0.f, 0.f);
            a1 = make_float4(0.f, 0.f, 0.f, 0.f);
        }
        float4 v0 = vals[(base + s) * 2 + 0];
        float4 v1 = vals[(base + s) * 2 + 1];
        a0.x += v0.x; a0.y += v0.y; a0.z += v0.z; a0.w += v0.w;
        a1.x += v1.x; a1.y += v1.y; a1.z += v1.z; a1.w += v1.w;
    }
    flush_ray(sums, cur, a0, a1);
}

__global__ void gather_kernel(const int* __restrict__ idx,
                              const float4* __restrict__ sums,   // 2 float4 per ray
                              float4* __restrict__ out,          // 2 float4 per sample
                              long long n_units) {               // n_samples * 2
    long long j = (long long)blockIdx.x * blockDim.x + threadIdx.x;
    if (j >= n_units) return;
    int sample = (int)(j >> 1);
    int ray = __ldg(idx + sample);
    out[j] = sums[(long long)ray * 2 + (j & 1)];
}

extern "C" void kernel_launch(void* const* d_in, const int* in_sizes, int n_in,
                              void* d_out, int out_size) {
    const float4* vals = (const float4*)d_in[0];
    const int* idx = (const int*)d_in[1];

    int n_samples = in_sizes[1];                 // 4194304
    int n_rays = out_size / 8 - n_samples;       // 65536

    float* sums = (float*)d_out;                        // [n_rays*8]
    float4* out_ps = (float4*)((float*)d_out + (size_t)n_rays * 8);  // [n_samples*2] float4

    // 1) zero the per-ray region
    {
        int n4 = n_rays * 2;  // n_rays*8 floats / 4
        int threads = 256;
        int blocks = (n4 + threads - 1) / threads;
        zero_kernel<<<blocks, threads>>>((float4*)sums, n4);
    }

    // 2) segmented reduce with register run-accumulation
    {
        long long n_threads = ((long long)n_samples + RUN - 1) / RUN;
        int threads = 256;
        long long blocks = (n_threads + threads - 1) / threads;
        reduce_kernel<<<(unsigned)blocks, threads>>>(vals, idx, sums, n_samples);
    }

    // 3) gather per-ray sums back to every sample (float4 granularity)
    {
        long long n_units = (long long)n_samples * 2;
        int threads = 256;
        long long blocks = (n_units + threads - 1) / threads;
        gather_kernel<<<(unsigned)blocks, threads>>>(idx, (const float4*)sums, out_ps, n_units);
    }
}

// round 4
// speedup vs baseline: 1.1265x; 1.1265x over previous
#include <cuda_runtime.h>

// Segment-sum over sorted ray_indices + gather back.
// Inputs: d_in[0] = sample_values  (float32, n_samples*8)
//         d_in[1] = ray_indices    (int32,  n_samples, sorted ascending)
//         d_in[2] = n_rays         (int32 scalar; derived from sizes instead)
// Output: d_out[0 .. n_rays*8)                    = per-ray sums
//         d_out[n_rays*8 .. n_rays*8+n_samples*8) = per-sample gathered sums

#define RUN 16  // consecutive samples per thread in the reduce pass

// Vectorized global reduction: one 128-bit RED instead of 4 scalar ones.
__device__ __forceinline__ void red_v4(float* p, float4 a) {
    asm volatile("red.global.add.v4.f32 [%0], {%1, %2, %3, %4};"
                 :: "l"(p), "f"(a.x), "f"(a.y), "f"(a.z), "f"(a.w)
                 : "memory");
}

__device__ __forceinline__ void flush_ray(float* __restrict__ sums, int ray,
                                          const float4& a0, const float4& a1) {
    float* p = sums + (size_t)ray * 8;
    red_v4(p, a0);
    red_v4(p + 4, a1);
}

__global__ void __launch_bounds__(256)
reduce_kernel(const float4* __restrict__ vals,   // 2 float4 per sample
              const int* __restrict__ idx,
              float* __restrict__ sums,          // [n_rays*8], pre-zeroed
              int n_samples) {
    long long t = (long long)blockIdx.x * blockDim.x + threadIdx.x;
    long long base = t * RUN;
    if (base >= n_samples) return;

    const bool full = (base + RUN <= n_samples);

    int ridx[RUN];
    if (full) {
        const int4* idx4 = reinterpret_cast<const int4*>(idx + base);
        #pragma unroll
        for (int q = 0; q < RUN / 4; q++) {
            int4 v = idx4[q];
            ridx[q * 4 + 0] = v.x;
            ridx[q * 4 + 1] = v.y;
            ridx[q * 4 + 2] = v.z;
            ridx[q * 4 + 3] = v.w;
        }
    } else {
        int cnt = (int)(n_samples - base);
        for (int s = 0; s < RUN; s++)
            ridx[s] = (s < cnt) ? idx[base + s] : -1;
    }

    int cur = ridx[0];
    float4 a0 = make_float4(0.f, 0.f, 0.f, 0.f);
    float4 a1 = make_float4(0.f, 0.f, 0.f, 0.f);

    if (full) {
        // Two half-batches of 8 samples: hoist all 16 float4 loads up front
        // (MLP=16), then accumulate. No data-dependent break -> ptxas batches.
        #pragma unroll
        for (int h = 0; h < RUN / 8; h++) {
            float4 v[16];
            const float4* vp = vals + (base + h * 8) * 2;
            #pragma unroll
            for (int i = 0; i < 16; i++) v[i] = vp[i];

            #pragma unroll
            for (int s = 0; s < 8; s++) {
                int r = ridx[h * 8 + s];
                if (r != cur) {
                    flush_ray(sums, cur, a0, a1);
                    cur = r;
                    a0 = make_float4(0.f, 0.f, 0.f, 0.f);
                    a1 = make_float4(0.f, 0.f, 0.f, 0.f);
                }
                float4 v0 = v[s * 2 + 0];
                float4 v1 = v[s * 2 + 1];
                a0.x += v0.x; a0.y += v0.y; a0.z += v0.z; a0.w += v0.w;
                a1.x += v1.x; a1.y += v1.y; a1.z += v1.z; a1.w += v1.w;
            }
        }
    } else {
        int cnt = (int)(n_samples - base);
        for (int s = 0; s < cnt; s++) {
            int r = ridx[s];
            if (r != cur) {
                flush_ray(sums, cur, a0, a1);
                cur = r;
                a0 = make_float4(0.f, 0.f, 0.f, 0.f);
                a1 = make_float4(0.f, 0.f, 0.f, 0.f);
            }
            float4 v0 = vals[(base + s) * 2 + 0];
            float4 v1 = vals[(base + s) * 2 + 1];
            a0.x += v0.x; a0.y += v0.y; a0.z += v0.z; a0.w += v0.w;
            a1.x += v1.x; a1.y += v1.y; a1.z += v1.z; a1.w += v1.w;
        }
    }
    flush_ray(sums, cur, a0, a1);
}

__global__ void __launch_bounds__(256)
gather_kernel(const int* __restrict__ idx,
              const float4* __restrict__ sums,   // 2 float4 per ray
              float4* __restrict__ out,          // 2 float4 per sample
              long long n_units) {               // n_samples * 2
    long long j = (long long)blockIdx.x * blockDim.x + threadIdx.x;
    if (j >= n_units) return;
    int sample = (int)(j >> 1);
    int ray = __ldg(idx + sample);
    out[j] = sums[(long long)ray * 2 + (j & 1)];
}

extern "C" void kernel_launch(void* const* d_in, const int* in_sizes, int n_in,
                              void* d_out, int out_size) {
    const float4* vals = (const float4*)d_in[0];
    const int* idx = (const int*)d_in[1];

    int n_samples = in_sizes[1];                 // 4194304
    int n_rays = out_size / 8 - n_samples;       // 65536

    float* sums = (float*)d_out;                                      // [n_rays*8]
    float4* out_ps = (float4*)((float*)d_out + (size_t)n_rays * 8);   // [n_samples*2] float4

    // 1) zero the per-ray region (memset node: no launch-latency-bound kernel)
    cudaMemsetAsync(d_out, 0, (size_t)n_rays * 8 * sizeof(float));

    // 2) segmented reduce: register run-accumulation + vectorized RED flushes
    {
        long long n_threads = ((long long)n_samples + RUN - 1) / RUN;
        int threads = 256;
        long long blocks = (n_threads + threads - 1) / threads;
        reduce_kernel<<<(unsigned)blocks, threads>>>(vals, idx, sums, n_samples);
    }

    // 3) gather per-ray sums back to every sample (float4 granularity)
    {
        long long n_units = (long long)n_samples * 2;
        int threads = 256;
        long long blocks = (n_units + threads - 1) / threads;
        gather_kernel<<<(unsigned)blocks, threads>>>(idx, (const float4*)sums, out_ps, n_units);
    }
}

// round 5
// speedup vs baseline: 1.2961x; 1.1505x over previous
#include <cuda_runtime.h>

// Segment-sum over sorted ray_indices + gather back.
// Inputs: d_in[0] = sample_values  (float32, n_samples*8)
//         d_in[1] = ray_indices    (int32,  n_samples, sorted ascending)
//         d_in[2] = n_rays         (int32 scalar; derived from sizes instead)
// Output: d_out[0 .. n_rays*8)                    = per-ray sums
//         d_out[n_rays*8 .. n_rays*8+n_samples*8) = per-sample gathered sums

#define RBLOCK 256
#define RUN 8                       // samples per thread
#define S_SAMPLES (RBLOCK * RUN)    // 2048 samples per block
#define S_F4 (S_SAMPLES * 2)        // 4096 float4 = 64 KB dynamic smem

// Swizzle in float4 units: XOR low 3 bits with bits [4:7). Makes both the
// coalesced staging stores (consecutive i per warp) and the per-thread
// stride-16-float4 LDS.128 reads bank-conflict-free.
__device__ __forceinline__ int swz(int i) { return i ^ ((i >> 4) & 7); }

// Vectorized global reduction: one 128-bit RED instead of 4 scalar ones.
__device__ __forceinline__ void red_v4(float* p, float4 a) {
    asm volatile("red.global.add.v4.f32 [%0], {%1, %2, %3, %4};"
                 :: "l"(p), "f"(a.x), "f"(a.y), "f"(a.z), "f"(a.w)
                 : "memory");
}

__device__ __forceinline__ void flush_ray(float* __restrict__ sums, int ray,
                                          const float4& a0, const float4& a1) {
    float* p = sums + (size_t)ray * 8;
    red_v4(p, a0);
    red_v4(p + 4, a1);
}

__global__ void __launch_bounds__(RBLOCK)
reduce_kernel(const float4* __restrict__ vals,   // 2 float4 per sample
              const int* __restrict__ idx,
              float* __restrict__ sums,          // [n_rays*8], pre-zeroed
              int n_samples) {
    extern __shared__ float4 sh[];               // S_F4 float4 (64 KB)
    const int tid = threadIdx.x;
    const long long base = (long long)blockIdx.x * S_SAMPLES;
    if (base >= n_samples) return;

    const bool full = (base + S_SAMPLES <= n_samples);
    const long long gbase4 = base * 2;           // float4 index of block start

    // ---- Stage values into smem, perfectly coalesced ----
    if (full) {
        #pragma unroll
        for (int j = 0; j < S_F4 / RBLOCK; j++) {
            int i = tid + j * RBLOCK;
            sh[swz(i)] = vals[gbase4 + i];
        }
    } else {
        int cnt4 = (int)(n_samples - base) * 2;
        for (int i = tid; i < cnt4; i += RBLOCK)
            sh[swz(i)] = vals[gbase4 + i];
    }
    __syncthreads();

    // ---- Per-thread run of RUN consecutive samples ----
    const long long sbase = base + (long long)tid * RUN;
    if (sbase >= n_samples) return;
    const int cnt = (int)((sbase + RUN <= n_samples) ? RUN : (n_samples - sbase));

    int ridx[RUN];
    if (cnt == RUN) {
        const int4* idx4 = reinterpret_cast<const int4*>(idx + sbase);
        #pragma unroll
        for (int q = 0; q < RUN / 4; q++) {
            int4 v = idx4[q];
            ridx[q * 4 + 0] = v.x;
            ridx[q * 4 + 1] = v.y;
            ridx[q * 4 + 2] = v.z;
            ridx[q * 4 + 3] = v.w;
        }
    } else {
        for (int s = 0; s < RUN; s++)
            ridx[s] = (s < cnt) ? idx[sbase + s] : -1;
    }

    int cur = ridx[0];
    float4 a0 = make_float4(0.f, 0.f, 0.f, 0.f);
    float4 a1 = make_float4(0.f, 0.f, 0.f, 0.f);

    const int lbase = tid * (RUN * 2);           // this thread's float4 region in smem
    #pragma unroll
    for (int s = 0; s < RUN; s++) {
        if (s >= cnt) break;
        int r = ridx[s];
        if (r != cur) {
            flush_ray(sums, cur, a0, a1);
            cur = r;
            a0 = make_float4(0.f, 0.f, 0.f, 0.f);
            a1 = make_float4(0.f, 0.f, 0.f, 0.f);
        }
        float4 v0 = sh[swz(lbase + s * 2 + 0)];
        float4 v1 = sh[swz(lbase + s * 2 + 1)];
        a0.x += v0.x; a0.y += v0.y; a0.z += v0.z; a0.w += v0.w;
        a1.x += v1.x; a1.y += v1.y; a1.z += v1.z; a1.w += v1.w;
    }
    flush_ray(sums, cur, a0, a1);
}

#define GILP 4

__global__ void __launch_bounds__(256)
gather_kernel(const int* __restrict__ idx,
              const float4* __restrict__ sums,   // 2 float4 per ray
              float4* __restrict__ out,          // 2 float4 per sample
              long long n_units) {               // n_samples * 2
    const long long j0 = (long long)blockIdx.x * blockDim.x + threadIdx.x;
    const long long stride = (long long)gridDim.x * blockDim.x;

    long long jj[GILP];
    int ray[GILP];
    bool ok[GILP];
    #pragma unroll
    for (int k = 0; k < GILP; k++) {
        jj[k] = j0 + k * stride;
        ok[k] = jj[k] < n_units;
        ray[k] = ok[k] ? __ldg(idx + (jj[k] >> 1)) : 0;
    }
    float4 v[GILP];
    #pragma unroll
    for (int k = 0; k < GILP; k++)
        if (ok[k]) v[k] = sums[(long long)ray[k] * 2 + (jj[k] & 1)];
    #pragma unroll
    for (int k = 0; k < GILP; k++)
        if (ok[k]) out[jj[k]] = v[k];
}

extern "C" void kernel_launch(void* const* d_in, const int* in_sizes, int n_in,
                              void* d_out, int out_size) {
    const float4* vals = (const float4*)d_in[0];
    const int* idx = (const int*)d_in[1];

    int n_samples = in_sizes[1];                 // 4194304
    int n_rays = out_size / 8 - n_samples;       // 65536

    float* sums = (float*)d_out;                                      // [n_rays*8]
    float4* out_ps = (float4*)((float*)d_out + (size_t)n_rays * 8);   // [n_samples*2] float4

    // 1) zero the per-ray region (memset node)
    cudaMemsetAsync(d_out, 0, (size_t)n_rays * 8 * sizeof(float));

    // 2) segmented reduce: smem-staged coalesced loads + register run
    //    accumulation + vectorized RED flushes
    {
        static bool attr_set = false;
        if (!attr_set) {
            cudaFuncSetAttribute(reduce_kernel,
                                 cudaFuncAttributeMaxDynamicSharedMemorySize,
                                 S_F4 * sizeof(float4));
            attr_set = true;
        }
        long long blocks = ((long long)n_samples + S_SAMPLES - 1) / S_SAMPLES;
        reduce_kernel<<<(unsigned)blocks, RBLOCK, S_F4 * sizeof(float4)>>>(
            vals, idx, sums, n_samples);
    }

    // 3) gather per-ray sums back to every sample, 4-way ILP, coalesced stores
    {
        long long n_units = (long long)n_samples * 2;
        int threads = 256;
        long long total_thr = (n_units + GILP - 1) / GILP;
        long long blocks = (total_thr + threads - 1) / threads;
        gather_kernel<<<(unsigned)blocks, threads>>>(idx, (const float4*)sums,
                                                     out_ps, n_units);
    }
}

// round 6
// speedup vs baseline: 1.3384x; 1.0326x over previous
#include <cuda_runtime.h>

// Segment-sum over sorted ray_indices + gather back.
// Inputs: d_in[0] = sample_values  (float32, n_samples*8)
//         d_in[1] = ray_indices    (int32,  n_samples, sorted ascending)
//         d_in[2] = n_rays         (int32 scalar; derived from sizes instead)
// Output: d_out[0 .. n_rays*8)                    = per-ray sums
//         d_out[n_rays*8 .. n_rays*8+n_samples*8) = per-sample gathered sums

// ---------------- reduce config ----------------
#define RBLOCK 128
#define RUN 8                        // samples per thread
#define R_SAMPLES (RBLOCK * RUN)     // 1024 samples per block
#define R_F4 (R_SAMPLES * 2)         // 2048 float4 = 32 KB smem

// thread value region stride = RUN*2 = 16 float4 -> swizzle on bits [4:7)
__device__ __forceinline__ int swz16(int i) { return i ^ ((i >> 4) & 7); }

// ---------------- gather config ----------------
#define GBLOCK 256
#define GRUN 4                       // samples per thread
#define G_SAMPLES (GBLOCK * GRUN)    // 1024 samples per block
#define G_F4 (G_SAMPLES * 2)         // 2048 float4 = 32 KB smem

// thread region stride = GRUN*2 = 8 float4 -> swizzle on bits [3:6)
__device__ __forceinline__ int swz8(int i) { return i ^ ((i >> 3) & 7); }

// Vectorized global reduction. NOTE: no "memory" clobber — inputs are pure
// register values and RED ops commute; volatile alone prevents elimination.
// This lets ptxas batch shared-memory loads across flush points.
__device__ __forceinline__ void red_v4(float* p, float4 a) {
    asm volatile("red.global.add.v4.f32 [%0], {%1, %2, %3, %4};"
                 :: "l"(p), "f"(a.x), "f"(a.y), "f"(a.z), "f"(a.w));
}

__device__ __forceinline__ void flush_ray(float* __restrict__ sums, int ray,
                                          const float4& a0, const float4& a1) {
    float* p = sums + (size_t)ray * 8;
    red_v4(p, a0);
    red_v4(p + 4, a1);
}

__global__ void __launch_bounds__(RBLOCK)
reduce_kernel(const float4* __restrict__ vals,   // 2 float4 per sample
              const int* __restrict__ idx,
              float* __restrict__ sums,          // [n_rays*8], pre-zeroed
              int n_samples) {
    extern __shared__ float4 sh[];               // R_F4 float4 (32 KB)
    const int tid = threadIdx.x;
    const long long base = (long long)blockIdx.x * R_SAMPLES;
    if (base >= n_samples) return;

    const bool full = (base + R_SAMPLES <= n_samples);
    const long long gbase4 = base * 2;

    // ---- Stage values into smem, perfectly coalesced ----
    if (full) {
        #pragma unroll
        for (int j = 0; j < R_F4 / RBLOCK; j++) {
            int i = tid + j * RBLOCK;
            sh[swz16(i)] = vals[gbase4 + i];
        }
    } else {
        int cnt4 = (int)(n_samples - base) * 2;
        for (int i = tid; i < cnt4; i += RBLOCK)
            sh[swz16(i)] = vals[gbase4 + i];
    }
    __syncthreads();

    const long long sbase = base + (long long)tid * RUN;
    if (sbase >= n_samples) return;
    const int cnt = (int)((sbase + RUN <= n_samples) ? RUN : (n_samples - sbase));

    int ridx[RUN];
    if (cnt == RUN) {
        const int4* idx4 = reinterpret_cast<const int4*>(idx + sbase);
        #pragma unroll
        for (int q = 0; q < RUN / 4; q++) {
            int4 v = idx4[q];
            ridx[q * 4 + 0] = v.x;
            ridx[q * 4 + 1] = v.y;
            ridx[q * 4 + 2] = v.z;
            ridx[q * 4 + 3] = v.w;
        }
    } else {
        for (int s = 0; s < RUN; s++)
            ridx[s] = (s < cnt) ? idx[sbase + s] : -1;
    }

    int cur = ridx[0];
    float4 a0 = make_float4(0.f, 0.f, 0.f, 0.f);
    float4 a1 = make_float4(0.f, 0.f, 0.f, 0.f);
    const int lbase = tid * (RUN * 2);

    if (cnt == RUN) {
        // Two half-batches of 4 samples; register-load all 8 float4 up front
        // so LDS latency pipelines across flush points.
        #pragma unroll
        for (int h = 0; h < 2; h++) {
            float4 v[8];
            #pragma unroll
            for (int i = 0; i < 8; i++)
                v[i] = sh[swz16(lbase + h * 8 + i)];
            #pragma unroll
            for (int s = 0; s < 4; s++) {
                int r = ridx[h * 4 + s];
                if (r != cur) {
                    flush_ray(sums, cur, a0, a1);
                    cur = r;
                    a0 = make_float4(0.f, 0.f, 0.f, 0.f);
                    a1 = make_float4(0.f, 0.f, 0.f, 0.f);
                }
                float4 v0 = v[s * 2 + 0];
                float4 v1 = v[s * 2 + 1];
                a0.x += v0.x; a0.y += v0.y; a0.z += v0.z; a0.w += v0.w;
                a1.x += v1.x; a1.y += v1.y; a1.z += v1.z; a1.w += v1.w;
            }
        }
    } else {
        for (int s = 0; s < cnt; s++) {
            int r = ridx[s];
            if (r != cur) {
                flush_ray(sums, cur, a0, a1);
                cur = r;
                a0 = make_float4(0.f, 0.f, 0.f, 0.f);
                a1 = make_float4(0.f, 0.f, 0.f, 0.f);
            }
            float4 v0 = sh[swz16(lbase + s * 2 + 0)];
            float4 v1 = sh[swz16(lbase + s * 2 + 1)];
            a0.x += v0.x; a0.y += v0.y; a0.z += v0.z; a0.w += v0.w;
            a1.x += v1.x; a1.y += v1.y; a1.z += v1.z; a1.w += v1.w;
        }
    }
    flush_ray(sums, cur, a0, a1);
}

__global__ void __launch_bounds__(GBLOCK)
gather_kernel(const int* __restrict__ idx,
              const float4* __restrict__ sums,   // 2 float4 per ray
              float4* __restrict__ out,          // 2 float4 per sample
              int n_samples) {
    extern __shared__ float4 sh[];               // G_F4 float4 (32 KB)
    const int tid = threadIdx.x;
    const long long base = (long long)blockIdx.x * G_SAMPLES;
    if (base >= n_samples) return;

    const long long sbase = base + (long long)tid * GRUN;
    if (sbase < n_samples) {
        const int cnt = (int)((sbase + GRUN <= n_samples) ? GRUN
                                                          : (n_samples - sbase));
        int ridx[GRUN];
        if (cnt == GRUN) {
            int4 v = *reinterpret_cast<const int4*>(idx + sbase);
            ridx[0] = v.x; ridx[1] = v.y; ridx[2] = v.z; ridx[3] = v.w;
        } else {
            for (int s = 0; s < GRUN; s++)
                ridx[s] = (s < cnt) ? idx[sbase + s] : -1;
        }

        // Load per-ray sums only on ray change (sorted -> ~1 ray per thread).
        int cur = -1;
        float4 s0 = make_float4(0.f, 0.f, 0.f, 0.f);
        float4 s1 = s0;
        const int lbase = tid * (GRUN * 2);
        #pragma unroll
        for (int s = 0; s < GRUN; s++) {
            if (s >= cnt) break;
            int r = ridx[s];
            if (r != cur) {
                s0 = __ldg(sums + (long long)r * 2 + 0);
                s1 = __ldg(sums + (long long)r * 2 + 1);
                cur = r;
            }
            sh[swz8(lbase + s * 2 + 0)] = s0;
            sh[swz8(lbase + s * 2 + 1)] = s1;
        }
    }
    __syncthreads();

    // Coalesced streaming write-out.
    const long long gbase4 = base * 2;
    if (base + G_SAMPLES <= n_samples) {
        #pragma unroll
        for (int j = 0; j < G_F4 / GBLOCK; j++) {
            int i = tid + j * GBLOCK;
            out[gbase4 + i] = sh[swz8(i)];
        }
    } else {
        int cnt4 = (int)(n_samples - base) * 2;
        for (int i = tid; i < cnt4; i += GBLOCK)
            out[gbase4 + i] = sh[swz8(i)];
    }
}

extern "C" void kernel_launch(void* const* d_in, const int* in_sizes, int n_in,
                              void* d_out, int out_size) {
    const float4* vals = (const float4*)d_in[0];
    const int* idx = (const int*)d_in[1];

    int n_samples = in_sizes[1];                 // 4194304
    int n_rays = out_size / 8 - n_samples;       // 65536

    float* sums = (float*)d_out;                                      // [n_rays*8]
    float4* out_ps = (float4*)((float*)d_out + (size_t)n_rays * 8);   // [n_samples*2] float4

    // 1) zero the per-ray region (memset node)
    cudaMemsetAsync(d_out, 0, (size_t)n_rays * 8 * sizeof(float));

    // 2) segmented reduce
    {
        long long blocks = ((long long)n_samples + R_SAMPLES - 1) / R_SAMPLES;
        reduce_kernel<<<(unsigned)blocks, RBLOCK, R_F4 * sizeof(float4)>>>(
            vals, idx, sums, n_samples);
    }

    // 3) run-aware gather with coalesced smem-staged stores
    {
        long long blocks = ((long long)n_samples + G_SAMPLES - 1) / G_SAMPLES;
        gather_kernel<<<(unsigned)blocks, GBLOCK, G_F4 * sizeof(float4)>>>(
            idx, (const float4*)sums, out_ps, n_samples);
    }
}

// round 7
// speedup vs baseline: 1.4504x; 1.0837x over previous
#include <cuda_runtime.h>

// Segment-sum over sorted ray_indices + gather back.
// Inputs: d_in[0] = sample_values  (float32, n_samples*8)
//         d_in[1] = ray_indices    (int32,  n_samples, sorted ascending)
//         d_in[2] = n_rays         (int32 scalar; derived from sizes instead)
// Output: d_out[0 .. n_rays*8)                    = per-ray sums
//         d_out[n_rays*8 .. n_rays*8+n_samples*8) = per-sample gathered sums
//
// Strategy: sorted indices => each ray is a contiguous pack. Compute pack
// offsets (one streaming pass), then one-warp-per-ray coalesced sum with a
// parity-preserving butterfly (NO atomics, NO memset), then a run-aware
// smem-staged gather. Offsets scratch lives in the (not yet written) tail
// of d_out.

// ---------------- boundary kernel ----------------
#define BBLOCK 256
#define BRUN 8
#define B_SAMPLES (BBLOCK * BRUN)

__global__ void __launch_bounds__(BBLOCK)
boundary_kernel(const int* __restrict__ idx,
                int* __restrict__ off,           // [n_rays+1]
                int n_samples, int n_rays) {
    long long base = ((long long)blockIdx.x * BBLOCK + threadIdx.x) * BRUN;
    if (base >= n_samples) return;
    int cnt = (int)((base + BRUN <= n_samples) ? BRUN : (n_samples - base));

    int r[BRUN];
    if (cnt == BRUN) {
        const int4* p = reinterpret_cast<const int4*>(idx + base);
        int4 v0 = p[0], v1 = p[1];
        r[0] = v0.x; r[1] = v0.y; r[2] = v0.z; r[3] = v0.w;
        r[4] = v1.x; r[5] = v1.y; r[6] = v1.z; r[7] = v1.w;
    } else {
        for (int s = 0; s < BRUN; s++) r[s] = (s < cnt) ? idx[base + s] : 0;
    }

    int prev = (base == 0) ? -1 : idx[base - 1];
    #pragma unroll
    for (int s = 0; s < BRUN; s++) {
        if (s >= cnt) break;
        if (r[s] != prev) {
            // fill (prev, r[s]] -> start = base+s  (also fills empty rays)
            for (int q = prev + 1; q <= r[s]; q++) off[q] = (int)(base + s);
        }
        prev = r[s];
    }
    if (base + cnt == n_samples) {
        // trailing empties + sentinel
        for (int q = prev + 1; q <= n_rays; q++) off[q] = n_samples;
    }
}

// ---------------- ray-sum kernel: one warp per ray ----------------
#define RSBLOCK 256
#define RAYS_PER_BLOCK (RSBLOCK / 32)

__global__ void __launch_bounds__(RSBLOCK)
raysum_kernel(const float4* __restrict__ vals,  // 2 float4 per sample
              const int* __restrict__ off,      // [n_rays+1]
              float4* __restrict__ sums,        // 2 float4 per ray
              int n_rays) {
    int warp = threadIdx.x >> 5;
    int lane = threadIdx.x & 31;
    int ray = blockIdx.x * RAYS_PER_BLOCK + warp;
    if (ray >= n_rays) return;

    long long a = (long long)off[ray] * 2;       // even -> lane parity == f4 parity
    long long b = (long long)off[ray + 1] * 2;

    float4 acc0 = make_float4(0.f, 0.f, 0.f, 0.f);
    float4 acc1 = acc0, acc2 = acc0, acc3 = acc0;

    long long j = a + lane;
    // 4-way unrolled coalesced streaming (evict-first: values are read-once)
    for (; j + 96 < b; j += 128) {
        float4 v0 = __ldcs(vals + j);
        float4 v1 = __ldcs(vals + j + 32);
        float4 v2 = __ldcs(vals + j + 64);
        float4 v3 = __ldcs(vals + j + 96);
        acc0.x += v0.x; acc0.y += v0.y; acc0.z += v0.z; acc0.w += v0.w;
        acc1.x += v1.x; acc1.y += v1.y; acc1.z += v1.z; acc1.w += v1.w;
        acc2.x += v2.x; acc2.y += v2.y; acc2.z += v2.z; acc2.w += v2.w;
        acc3.x += v3.x; acc3.y += v3.y; acc3.z += v3.z; acc3.w += v3.w;
    }
    for (; j < b; j += 32) {
        float4 v = __ldcs(vals + j);
        acc0.x += v.x; acc0.y += v.y; acc0.z += v.z; acc0.w += v.w;
    }
    acc0.x += acc1.x + acc2.x + acc3.x;
    acc0.y += acc1.y + acc2.y + acc3.y;
    acc0.z += acc1.z + acc2.z + acc3.z;
    acc0.w += acc1.w + acc2.w + acc3.w;

    // Butterfly over even strides only: lane parity (== f4 half) is preserved.
    #pragma unroll
    for (int d = 2; d < 32; d <<= 1) {
        acc0.x += __shfl_xor_sync(0xFFFFFFFFu, acc0.x, d);
        acc0.y += __shfl_xor_sync(0xFFFFFFFFu, acc0.y, d);
        acc0.z += __shfl_xor_sync(0xFFFFFFFFu, acc0.z, d);
        acc0.w += __shfl_xor_sync(0xFFFFFFFFu, acc0.w, d);
    }
    // lane 0 holds half-0 sum, lane 1 holds half-1 sum
    if (lane < 2) sums[(long long)ray * 2 + lane] = acc0;
}

// ---------------- gather kernel ----------------
#define GBLOCK 128
#define GRUN 4                        // samples per thread
#define G_SAMPLES (GBLOCK * GRUN)     // 512 samples per block
#define G_F4 (G_SAMPLES * 2)          // 1024 float4 = 16 KB smem

// thread region stride = GRUN*2 = 8 float4 -> swizzle bits [3:6) into [0:3)
__device__ __forceinline__ int swz8(int i) { return i ^ ((i >> 3) & 7); }

__global__ void __launch_bounds__(GBLOCK)
gather_kernel(const int* __restrict__ idx,
              const float4* __restrict__ sums,   // 2 float4 per ray
              float4* __restrict__ out,          // 2 float4 per sample
              int n_samples) {
    extern __shared__ float4 sh[];               // G_F4 float4 (16 KB)
    const int tid = threadIdx.x;
    const long long base = (long long)blockIdx.x * G_SAMPLES;
    if (base >= n_samples) return;

    const long long sbase = base + (long long)tid * GRUN;
    if (sbase < n_samples) {
        const int cnt = (int)((sbase + GRUN <= n_samples) ? GRUN
                                                          : (n_samples - sbase));
        int ridx[GRUN];
        if (cnt == GRUN) {
            int4 v = *reinterpret_cast<const int4*>(idx + sbase);
            ridx[0] = v.x; ridx[1] = v.y; ridx[2] = v.z; ridx[3] = v.w;
        } else {
            for (int s = 0; s < GRUN; s++)
                ridx[s] = (s < cnt) ? idx[sbase + s] : -1;
        }

        // Load per-ray sums only on ray change (sorted -> ~1 ray per thread).
        int cur = -1;
        float4 s0 = make_float4(0.f, 0.f, 0.f, 0.f);
        float4 s1 = s0;
        const int lbase = tid * (GRUN * 2);
        #pragma unroll
        for (int s = 0; s < GRUN; s++) {
            if (s >= cnt) break;
            int r = ridx[s];
            if (r != cur) {
                s0 = __ldg(sums + (long long)r * 2 + 0);
                s1 = __ldg(sums + (long long)r * 2 + 1);
                cur = r;
            }
            sh[swz8(lbase + s * 2 + 0)] = s0;
            sh[swz8(lbase + s * 2 + 1)] = s1;
        }
    }
    __syncthreads();

    // Coalesced streaming write-out (evict-first: keep idx/sums in L2).
    const long long gbase4 = base * 2;
    if (base + G_SAMPLES <= n_samples) {
        #pragma unroll
        for (int j = 0; j < G_F4 / GBLOCK; j++) {
            int i = tid + j * GBLOCK;
            __stcs(out + gbase4 + i, sh[swz8(i)]);
        }
    } else {
        int cnt4 = (int)(n_samples - base) * 2;
        for (int i = tid; i < cnt4; i += GBLOCK)
            __stcs(out + gbase4 + i, sh[swz8(i)]);
    }
}

extern "C" void kernel_launch(void* const* d_in, const int* in_sizes, int n_in,
                              void* d_out, int out_size) {
    const float4* vals = (const float4*)d_in[0];
    const int* idx = (const int*)d_in[1];

    int n_samples = in_sizes[1];                 // 4194304
    int n_rays = out_size / 8 - n_samples;       // 65536

    float4* sums = (float4*)d_out;                                    // [n_rays*2] float4
    float4* out_ps = (float4*)((float*)d_out + (size_t)n_rays * 8);   // [n_samples*2] float4
    // Scratch offsets live in the gather-output tail (written later by gather).
    int* off = (int*)out_ps;                                          // [n_rays+1] ints

    // 1) ray pack offsets (one streaming pass over idx)
    {
        long long blocks = ((long long)n_samples + B_SAMPLES - 1) / B_SAMPLES;
        boundary_kernel<<<(unsigned)blocks, BBLOCK>>>(idx, off, n_samples, n_rays);
    }

    // 2) one warp per ray, coalesced pack sum, no atomics
    {
        long long blocks = ((long long)n_rays + RAYS_PER_BLOCK - 1) / RAYS_PER_BLOCK;
        raysum_kernel<<<(unsigned)blocks, RSBLOCK>>>(vals, off, sums, n_rays);
    }

    // 3) run-aware gather with coalesced smem-staged stores
    {
        long long blocks = ((long long)n_samples + G_SAMPLES - 1) / G_SAMPLES;
        gather_kernel<<<(unsigned)blocks, GBLOCK, G_F4 * sizeof(float4)>>>(
            idx, (const float4*)sums, out_ps, n_samples);
    }
}

// round 8
// speedup vs baseline: 1.4974x; 1.0324x over previous
#include <cuda_runtime.h>

// Segment-sum over sorted ray_indices + gather back.
// Inputs: d_in[0] = sample_values  (float32, n_samples*8)
//         d_in[1] = ray_indices    (int32,  n_samples, sorted ascending)
//         d_in[2] = n_rays         (int32 scalar; derived from sizes instead)
// Output: d_out[0 .. n_rays*8)                    = per-ray sums
//         d_out[n_rays*8 .. n_rays*8+n_samples*8) = per-sample gathered sums
//
// Strategy: sorted indices => each ray is a contiguous pack.
//   1) boundary_kernel: one streaming pass over idx -> pack offsets in a
//      static __device__ scratch array (no alloc).
//   2) fused raysum+scatter: one warp per ray reads its pack coalesced,
//      butterfly-reduces (parity-preserving), writes the per-ray sum AND
//      streams the broadcast sum over the ray's contiguous output region.
//      No atomics, no memset, no second idx read, no smem.

#define MAX_RAYS_PAD (1 << 20)
__device__ int g_off[MAX_RAYS_PAD + 1];

// ---------------- boundary kernel ----------------
#define BBLOCK 256
#define BRUN 8
#define B_SAMPLES (BBLOCK * BRUN)

__global__ void __launch_bounds__(BBLOCK)
boundary_kernel(const int* __restrict__ idx,
                int n_samples, int n_rays) {
    const int lane = threadIdx.x & 31;
    long long base = ((long long)blockIdx.x * BBLOCK + threadIdx.x) * BRUN;
    const bool active = base < n_samples;
    int cnt = 0;

    int r[BRUN];
    if (active) {
        cnt = (int)((base + BRUN <= n_samples) ? BRUN : (n_samples - base));
        if (cnt == BRUN) {
            const int4* p = reinterpret_cast<const int4*>(idx + base);
            int4 v0 = p[0], v1 = p[1];
            r[0] = v0.x; r[1] = v0.y; r[2] = v0.z; r[3] = v0.w;
            r[4] = v1.x; r[5] = v1.y; r[6] = v1.z; r[7] = v1.w;
        } else {
            for (int s = 0; s < BRUN; s++) r[s] = (s < cnt) ? idx[base + s] : 0;
        }
    } else {
        #pragma unroll
        for (int s = 0; s < BRUN; s++) r[s] = 0;
    }

    // prev = last element of the preceding thread (shuffle); only lane 0
    // falls back to a scalar global load.
    int prev = __shfl_up_sync(0xFFFFFFFFu, r[BRUN - 1], 1);
    if (lane == 0) prev = (base == 0) ? -1 : ((active) ? idx[base - 1] : 0);
    if (!active) return;

    #pragma unroll
    for (int s = 0; s < BRUN; s++) {
        if (s >= cnt) break;
        if (r[s] != prev) {
            // fill (prev, r[s]] -> start = base+s (also fills empty rays)
            for (int q = prev + 1; q <= r[s]; q++) g_off[q] = (int)(base + s);
        }
        prev = r[s];
    }
    if (base + cnt == n_samples) {
        for (int q = prev + 1; q <= n_rays; q++) g_off[q] = n_samples;
    }
}

// ------- fused ray-sum + scatter kernel: one warp per ray -------
#define RSBLOCK 256
#define RAYS_PER_BLOCK (RSBLOCK / 32)

__global__ void __launch_bounds__(RSBLOCK)
raysum_scatter_kernel(const float4* __restrict__ vals,  // 2 float4 per sample
                      float4* __restrict__ sums,        // 2 float4 per ray
                      float4* __restrict__ out,         // 2 float4 per sample
                      int n_rays) {
    int warp = threadIdx.x >> 5;
    int lane = threadIdx.x & 31;
    int ray = blockIdx.x * RAYS_PER_BLOCK + warp;
    if (ray >= n_rays) return;

    long long a2 = (long long)g_off[ray] * 2;     // even -> lane parity == f4 parity
    long long b2 = (long long)g_off[ray + 1] * 2;

    float4 acc0 = make_float4(0.f, 0.f, 0.f, 0.f);
    float4 acc1 = acc0, acc2 = acc0, acc3 = acc0;

    long long j = a2 + lane;
    // 4-way unrolled coalesced streaming (evict-first: values are read-once)
    for (; j + 96 < b2; j += 128) {
        float4 v0 = __ldcs(vals + j);
        float4 v1 = __ldcs(vals + j + 32);
        float4 v2 = __ldcs(vals + j + 64);
        float4 v3 = __ldcs(vals + j + 96);
        acc0.x += v0.x; acc0.y += v0.y; acc0.z += v0.z; acc0.w += v0.w;
        acc1.x += v1.x; acc1.y += v1.y; acc1.z += v1.z; acc1.w += v1.w;
        acc2.x += v2.x; acc2.y += v2.y; acc2.z += v2.z; acc2.w += v2.w;
        acc3.x += v3.x; acc3.y += v3.y; acc3.z += v3.z; acc3.w += v3.w;
    }
    for (; j < b2; j += 32) {
        float4 v = __ldcs(vals + j);
        acc0.x += v.x; acc0.y += v.y; acc0.z += v.z; acc0.w += v.w;
    }
    acc0.x += acc1.x + acc2.x + acc3.x;
    acc0.y += acc1.y + acc2.y + acc3.y;
    acc0.z += acc1.z + acc2.z + acc3.z;
    acc0.w += acc1.w + acc2.w + acc3.w;

    // Butterfly over even strides only: every lane ends with the total for
    // its own parity (lane parity == float4-half parity).
    #pragma unroll
    for (int d = 2; d < 32; d <<= 1) {
        acc0.x += __shfl_xor_sync(0xFFFFFFFFu, acc0.x, d);
        acc0.y += __shfl_xor_sync(0xFFFFFFFFu, acc0.y, d);
        acc0.z += __shfl_xor_sync(0xFFFFFFFFu, acc0.z, d);
        acc0.w += __shfl_xor_sync(0xFFFFFFFFu, acc0.w, d);
    }

    // Per-ray sum: lane 0 holds half-0, lane 1 holds half-1.
    if (lane < 2) sums[(long long)ray * 2 + lane] = acc0;

    // Scatter: stream the broadcast sum over the ray's contiguous output
    // region. out[j] parity == lane parity, so each lane stores its acc0.
    j = a2 + lane;
    for (; j + 96 < b2; j += 128) {
        __stcs(out + j, acc0);
        __stcs(out + j + 32, acc0);
        __stcs(out + j + 64, acc0);
        __stcs(out + j + 96, acc0);
    }
    for (; j < b2; j += 32) __stcs(out + j, acc0);
}

extern "C" void kernel_launch(void* const* d_in, const int* in_sizes, int n_in,
                              void* d_out, int out_size) {
    const float4* vals = (const float4*)d_in[0];
    const int* idx = (const int*)d_in[1];

    int n_samples = in_sizes[1];                 // 4194304
    int n_rays = out_size / 8 - n_samples;       // 65536

    float4* sums = (float4*)d_out;                                    // [n_rays*2] float4
    float4* out_ps = (float4*)((float*)d_out + (size_t)n_rays * 8);   // [n_samples*2] float4

    // 1) ray pack offsets (one streaming pass over idx)
    {
        long long blocks = ((long long)n_samples + B_SAMPLES - 1) / B_SAMPLES;
        boundary_kernel<<<(unsigned)blocks, BBLOCK>>>(idx, n_samples, n_rays);
    }

    // 2) fused: one warp per ray -> sum + per-ray write + scatter write
    {
        long long blocks = ((long long)n_rays + RAYS_PER_BLOCK - 1) / RAYS_PER_BLOCK;
        raysum_scatter_kernel<<<(unsigned)blocks, RSBLOCK>>>(vals, sums, out_ps,
                                                             n_rays);
    }
}

// round 9
// speedup vs baseline: 1.8148x; 1.2120x over previous
#include <cuda_runtime.h>

// Segment-sum over sorted ray_indices + gather back.
// Output: d_out[0 .. n_rays*8)                    = per-ray sums
//         d_out[n_rays*8 .. n_rays*8+n_samples*8) = per-sample gathered sums
//
// Sorted indices => each ray is a contiguous pack.
//   1) boundary_kernel: streaming pass over idx -> pack offsets (static
//      __device__ scratch, no alloc).
//   2) fused raysum+scatter: one warp per ray, coalesced pack read,
//      parity-preserving butterfly, per-ray sum write + broadcast scatter.
//      All 32-bit indexing; tuned for 7 blocks/SM.

#define MAX_RAYS_PAD (1 << 20)
__device__ int g_off[MAX_RAYS_PAD + 1];

// ---------------- boundary kernel ----------------
#define BBLOCK 256
#define BRUN 16
#define B_SAMPLES (BBLOCK * BRUN)

__global__ void __launch_bounds__(BBLOCK)
boundary_kernel(const int* __restrict__ idx,
                int n_samples, int n_rays) {
    const int lane = threadIdx.x & 31;
    int base = (blockIdx.x * BBLOCK + threadIdx.x) * BRUN;
    const bool active = base < n_samples;
    int cnt = 0;

    int r[BRUN];
    if (active) {
        cnt = (base + BRUN <= n_samples) ? BRUN : (n_samples - base);
        if (cnt == BRUN) {
            const int4* p = reinterpret_cast<const int4*>(idx + base);
            int4 v0 = p[0], v1 = p[1], v2 = p[2], v3 = p[3];
            r[0]  = v0.x; r[1]  = v0.y; r[2]  = v0.z; r[3]  = v0.w;
            r[4]  = v1.x; r[5]  = v1.y; r[6]  = v1.z; r[7]  = v1.w;
            r[8]  = v2.x; r[9]  = v2.y; r[10] = v2.z; r[11] = v2.w;
            r[12] = v3.x; r[13] = v3.y; r[14] = v3.z; r[15] = v3.w;
        } else {
            for (int s = 0; s < BRUN; s++) r[s] = (s < cnt) ? idx[base + s] : 0;
        }
    } else {
        #pragma unroll
        for (int s = 0; s < BRUN; s++) r[s] = 0;
    }

    // prev = preceding thread's last element via shuffle; only lane 0 does a
    // scalar global load.
    int prev = __shfl_up_sync(0xFFFFFFFFu, r[BRUN - 1], 1);
    if (lane == 0) prev = (base == 0) ? -1 : (active ? idx[base - 1] : 0);
    if (!active) return;

    #pragma unroll
    for (int s = 0; s < BRUN; s++) {
        if (s >= cnt) break;
        if (r[s] != prev) {
            for (int q = prev + 1; q <= r[s]; q++) g_off[q] = base + s;
        }
        prev = r[s];
    }
    if (base + cnt == n_samples) {
        for (int q = prev + 1; q <= n_rays; q++) g_off[q] = n_samples;
    }
}

// ------- fused ray-sum + scatter kernel: one warp per ray -------
#define RSBLOCK 256
#define RAYS_PER_BLOCK (RSBLOCK / 32)

__global__ void __launch_bounds__(RSBLOCK, 7)
raysum_scatter_kernel(const float4* __restrict__ vals,  // 2 float4 per sample
                      float4* __restrict__ sums,        // 2 float4 per ray
                      float4* __restrict__ out,         // 2 float4 per sample
                      int n_rays) {
    int warp = threadIdx.x >> 5;
    int lane = threadIdx.x & 31;
    int ray = blockIdx.x * RAYS_PER_BLOCK + warp;
    if (ray >= n_rays) return;

    // 32-bit indices: n_samples*2 = 8.4M fits comfortably.
    int a2 = g_off[ray] * 2;          // even -> lane parity == f4 parity
    int b2 = g_off[ray + 1] * 2;

    float4 acc0 = make_float4(0.f, 0.f, 0.f, 0.f);
    float4 acc1 = acc0;

    int j = a2 + lane;
    // 2-way unrolled coalesced streaming (mean pack = 128 f4 -> ~2 iters)
    for (; j + 32 < b2; j += 64) {
        float4 v0 = __ldcs(vals + j);
        float4 v1 = __ldcs(vals + j + 32);
        acc0.x += v0.x; acc0.y += v0.y; acc0.z += v0.z; acc0.w += v0.w;
        acc1.x += v1.x; acc1.y += v1.y; acc1.z += v1.z; acc1.w += v1.w;
    }
    if (j < b2) {
        float4 v = __ldcs(vals + j);
        acc0.x += v.x; acc0.y += v.y; acc0.z += v.z; acc0.w += v.w;
    }
    acc0.x += acc1.x; acc0.y += acc1.y; acc0.z += acc1.z; acc0.w += acc1.w;

    // Butterfly over even strides: every lane ends with the total for its
    // own parity (lane parity == float4-half parity).
    #pragma unroll
    for (int d = 2; d < 32; d <<= 1) {
        acc0.x += __shfl_xor_sync(0xFFFFFFFFu, acc0.x, d);
        acc0.y += __shfl_xor_sync(0xFFFFFFFFu, acc0.y, d);
        acc0.z += __shfl_xor_sync(0xFFFFFFFFu, acc0.z, d);
        acc0.w += __shfl_xor_sync(0xFFFFFFFFu, acc0.w, d);
    }

    // Per-ray sum: lane 0 holds half-0, lane 1 holds half-1.
    if (lane < 2) sums[ray * 2 + lane] = acc0;

    // Scatter the broadcast sum over the ray's contiguous output region.
    // out[j] parity == lane parity, so each lane stores its own acc0.
    j = a2 + lane;
    for (; j + 32 < b2; j += 64) {
        __stcs(out + j, acc0);
        __stcs(out + j + 32, acc0);
    }
    if (j < b2) __stcs(out + j, acc0);
}

extern "C" void kernel_launch(void* const* d_in, const int* in_sizes, int n_in,
                              void* d_out, int out_size) {
    const float4* vals = (const float4*)d_in[0];
    const int* idx = (const int*)d_in[1];

    int n_samples = in_sizes[1];                 // 4194304
    int n_rays = out_size / 8 - n_samples;       // 65536

    float4* sums = (float4*)d_out;                                    // [n_rays*2] float4
    float4* out_ps = (float4*)((float*)d_out + (size_t)n_rays * 8);   // [n_samples*2] float4

    // 1) ray pack offsets (one streaming pass over idx)
    {
        long long blocks = ((long long)n_samples + B_SAMPLES - 1) / B_SAMPLES;
        boundary_kernel<<<(unsigned)blocks, BBLOCK>>>(idx, n_samples, n_rays);
    }

    // 2) fused: one warp per ray -> sum + per-ray write + scatter write
    {
        long long blocks = ((long long)n_rays + RAYS_PER_BLOCK - 1) / RAYS_PER_BLOCK;
        raysum_scatter_kernel<<<(unsigned)blocks, RSBLOCK>>>(vals, sums, out_ps,
                                                             n_rays);
    }
}